// round 2
// baseline (speedup 1.0000x reference)
#include <cuda_runtime.h>
#include <cuda_bf16.h>

// GATv2WithLogits collapses algebraically:
//   x_j = x_proj[col] is constant within each softmax segment (also keyed by col),
//   so out[n] = x_proj[n] * (sum of softmax weights) = x_proj[n] * 1.0 for deg>0
//   nodes, and 0 for isolated nodes. Only W, x, and col matter:
//   out[n,c] = mask[n] * x[n] @ Wm[:,c],  Wm[k,c] = 0.25 * sum_h W[k, h*16+c]
//
// NOTE: edge_index is int32 on device (JAX x64 disabled downcasts the
// requested int64), so index with 4-byte strides.

#define MASK_BYTES 100096            // >= N=100000, multiple of 16
#define MASK_INTS  (MASK_BYTES / 4)  // 25024

__device__ unsigned char g_mask[MASK_BYTES];
__device__ float g_Wm[128 * 16];

// Zero the degree mask; block 0 also folds W [128,64] -> Wm [128,16] (mean over 4 heads).
__global__ void k_init(const float* __restrict__ W) {
    unsigned int tid = blockIdx.x * 256u + threadIdx.x;
    if (tid < MASK_INTS) ((int*)g_mask)[tid] = 0;
    if (blockIdx.x == 0) {
        #pragma unroll
        for (int i = threadIdx.x; i < 2048; i += 256) {
            int k = i >> 4;
            int c = i & 15;
            const float* w = W + k * 64 + c;
            g_Wm[i] = 0.25f * (w[0] + w[16] + w[32] + w[48]);
        }
    }
}

// mask[col[e]] = 1 for every edge destination. Races write the same value: benign.
__global__ void k_mark(const int* __restrict__ col, int E) {
    int i = blockIdx.x * 256 + threadIdx.x;
    if (i < E) {
        int c = col[i];
        if ((unsigned)c < (unsigned)MASK_BYTES) g_mask[c] = 1;
    }
}

// out[row, 0:16] = mask[row] * x[row] @ Wm.
// Thread layout: tid%4 = 4-channel chunk, tid/4 = local row (64 rows / 256-thread block).
// Per 4-k step: 1 LDG.128 of x (4 lanes share each address -> 128B/warp),
// 4 LDS.128 of Wm (multicast, conflict-free), 16 FFMA.
__global__ void __launch_bounds__(256) k_gemm(const float4* __restrict__ x4,
                                              float4* __restrict__ out4, int n) {
    __shared__ float ws[2048];  // Wm [128][16]
    {
        const float4* src = (const float4*)g_Wm;
        float4* dst = (float4*)ws;
        dst[threadIdx.x] = src[threadIdx.x];
        dst[threadIdx.x + 256] = src[threadIdx.x + 256];
    }
    __syncthreads();

    int c4 = threadIdx.x & 3;             // channel chunk: columns [c4*4, c4*4+4)
    int rlocal = threadIdx.x >> 2;
    int row = blockIdx.x * 64 + rlocal;
    int rowc = (row < n) ? row : 0;       // clamp for tail block; store is guarded
    const float4* xr = x4 + (size_t)rowc * 32;
    const float* wbase = ws + c4 * 4;

    float a0 = 0.f, a1 = 0.f, a2 = 0.f, a3 = 0.f;
    #pragma unroll
    for (int kq = 0; kq < 32; kq++) {
        float4 xv = xr[kq];
        float4 w0 = *(const float4*)(wbase + (kq * 4 + 0) * 16);
        float4 w1 = *(const float4*)(wbase + (kq * 4 + 1) * 16);
        float4 w2 = *(const float4*)(wbase + (kq * 4 + 2) * 16);
        float4 w3 = *(const float4*)(wbase + (kq * 4 + 3) * 16);
        a0 += xv.x * w0.x; a1 += xv.x * w0.y; a2 += xv.x * w0.z; a3 += xv.x * w0.w;
        a0 += xv.y * w1.x; a1 += xv.y * w1.y; a2 += xv.y * w1.z; a3 += xv.y * w1.w;
        a0 += xv.z * w2.x; a1 += xv.z * w2.y; a2 += xv.z * w2.z; a3 += xv.z * w2.w;
        a0 += xv.w * w3.x; a1 += xv.w * w3.y; a2 += xv.w * w3.z; a3 += xv.w * w3.w;
    }

    if (row < n) {
        float m = g_mask[row] ? 1.0f : 0.0f;
        float4 o;
        o.x = a0 * m; o.y = a1 * m; o.z = a2 * m; o.w = a3 * m;
        out4[(size_t)row * 4 + c4] = o;
    }
}

extern "C" void kernel_launch(void* const* d_in, const int* in_sizes, int n_in,
                              void* d_out, int out_size) {
    const float* x = (const float*)d_in[0];
    const int* ei = (const int*)d_in[1];   // [2, E] int32 on device
    const float* W = (const float*)d_in[2];
    // d_in[3] = att: provably irrelevant to the output (softmax weights sum to 1).
    (void)n_in;
    (void)out_size;

    int n = in_sizes[0] / 128;   // N = 100000
    int E = in_sizes[1] / 2;     // E = 1600000
    const int* col = ei + E;     // edge_index[1][:]

    k_init<<<(MASK_INTS + 255) / 256, 256>>>(W);
    k_mark<<<(E + 255) / 256, 256>>>(col, E);
    k_gemm<<<(n + 63) / 64, 256>>>((const float4*)x, (float4*)d_out, n);
}